// round 2
// baseline (speedup 1.0000x reference)
#include <cuda_runtime.h>
#include <math.h>
#include <stdint.h>

// Problem dims (fixed)
#define Bz 16
#define Tt 4096
#define Hd 512
#define G3 1536            // 3*Hd

// Scan kernel config
#define NB 128             // persistent blocks (one grid barrier per timestep)
#define NH 4               // hidden units per block (NB*NH = 512)
#define SCAN_THREADS 384
#define WS_STRIDE 520      // 512 + pad (breaks bank conflict between cc column groups)

// ---------------------------------------------------------------------------
// Scratch (device globals; no allocation allowed)
// ---------------------------------------------------------------------------
__device__ float g_xp[(size_t)Bz * Tt * G3];    // 402 MB: xp1, then reused for xp2
__device__ float g_a [(size_t)Bz * Tt * Hd];    // 134 MB: gelu(h1)
__device__ float g_h [2][Hd * Bz];              // ping-pong hidden state [k][b]
__device__ unsigned g_cnt = 0;
__device__ unsigned g_gen = 0;

// ---------------------------------------------------------------------------
// GEMM: C[M][1536] = A[M][512] * W[1536][512]^T + bias[1536]
// 128x128 block tile, K-chunk 16, 256 threads, 8x8 per thread (4+4 split).
// ---------------------------------------------------------------------------
__global__ __launch_bounds__(256, 1) void gemm_nt_bias(
    const float* __restrict__ A, const float* __restrict__ W,
    const float* __restrict__ bias, float* __restrict__ C)
{
    __shared__ float as[16][132];
    __shared__ float bs[16][132];

    const int m0 = blockIdx.y * 128;
    const int n0 = blockIdx.x * 128;
    const int tid = threadIdx.x;
    const int tx = tid & 15;        // n direction
    const int ty = tid >> 4;        // m direction

    float acc[8][8];
#pragma unroll
    for (int i = 0; i < 8; i++)
#pragma unroll
        for (int j = 0; j < 8; j++) acc[i][j] = 0.f;

    for (int kc = 0; kc < 512; kc += 16) {
        // Load tiles: 128 rows x 16 k each (512 float4 per tile, 2 per thread)
#pragma unroll
        for (int it = 0; it < 2; it++) {
            int f = tid + it * 256;          // 0..511
            int row = f >> 2;
            int kq = (f & 3) * 4;
            float4 va = *(const float4*)&A[(size_t)(m0 + row) * 512 + kc + kq];
            as[kq + 0][row] = va.x; as[kq + 1][row] = va.y;
            as[kq + 2][row] = va.z; as[kq + 3][row] = va.w;
            float4 vb = *(const float4*)&W[(size_t)(n0 + row) * 512 + kc + kq];
            bs[kq + 0][row] = vb.x; bs[kq + 1][row] = vb.y;
            bs[kq + 2][row] = vb.z; bs[kq + 3][row] = vb.w;
        }
        __syncthreads();

#pragma unroll
        for (int k = 0; k < 16; k++) {
            float a[8], b[8];
            *(float4*)&a[0] = *(const float4*)&as[k][ty * 4];
            *(float4*)&a[4] = *(const float4*)&as[k][64 + ty * 4];
            *(float4*)&b[0] = *(const float4*)&bs[k][tx * 4];
            *(float4*)&b[4] = *(const float4*)&bs[k][64 + tx * 4];
#pragma unroll
            for (int i = 0; i < 8; i++)
#pragma unroll
                for (int j = 0; j < 8; j++)
                    acc[i][j] = fmaf(a[i], b[j], acc[i][j]);
        }
        __syncthreads();
    }

    // Epilogue: rows m0 + (ty*4 + i | 64 + ty*4 + i), cols n0 + (tx*4 + j | 64 + ...)
    float4 bv0 = *(const float4*)&bias[n0 + tx * 4];
    float4 bv1 = *(const float4*)&bias[n0 + 64 + tx * 4];
#pragma unroll
    for (int i = 0; i < 8; i++) {
        int m = m0 + ((i < 4) ? (ty * 4 + i) : (64 + ty * 4 + (i - 4)));
        float4 o0, o1;
        o0.x = acc[i][0] + bv0.x; o0.y = acc[i][1] + bv0.y;
        o0.z = acc[i][2] + bv0.z; o0.w = acc[i][3] + bv0.w;
        o1.x = acc[i][4] + bv1.x; o1.y = acc[i][5] + bv1.y;
        o1.z = acc[i][6] + bv1.z; o1.w = acc[i][7] + bv1.w;
        *(float4*)&C[(size_t)m * G3 + n0 + tx * 4]      = o0;
        *(float4*)&C[(size_t)m * G3 + n0 + 64 + tx * 4] = o1;
    }
}

// ---------------------------------------------------------------------------
// Grid barrier (sense via monotonically increasing generation counter)
// ---------------------------------------------------------------------------
__device__ __forceinline__ void grid_barrier()
{
    __syncthreads();
    if (threadIdx.x == 0) {
        unsigned gen = *((volatile unsigned*)&g_gen);
        __threadfence();
        if (atomicAdd(&g_cnt, 1) == NB - 1) {
            g_cnt = 0;
            __threadfence();
            atomicAdd(&g_gen, 1);
        } else {
            while (*((volatile unsigned*)&g_gen) == gen) { __nanosleep(32); }
        }
        __threadfence();
    }
    __syncthreads();
}

__device__ __forceinline__ float sigmoidf_(float x) { return 1.0f / (1.0f + expf(-x)); }
__device__ __forceinline__ float gelu_erf(float x) {
    return 0.5f * x * (1.0f + erff(x * 0.70710678118654752f));
}

// ---------------------------------------------------------------------------
// Persistent GRU scan over T timesteps.
// Block b owns hidden units j0 = b*NH .. +NH-1 (12 gate rows of w_hh in smem).
// Shared h[k][b] reloaded from global ping-pong buffer each step.
// Threads: (s in {0,1} K-split) x (cc in [0,12)) x (b in [0,16)) = 384.
// ---------------------------------------------------------------------------
__global__ __launch_bounds__(SCAN_THREADS, 1) void gru_scan(
    const float* __restrict__ xp, const float* __restrict__ w_hh,
    const float* __restrict__ b_hh, float* __restrict__ out, int do_gelu)
{
    extern __shared__ float sm[];
    float* hs  = sm;                        // [512][16]  8192 floats
    float* ws  = sm + Hd * Bz;              // [12][WS_STRIDE]
    float* red = ws + 12 * WS_STRIDE;       // [2][12][16] 384 floats

    const int tid = threadIdx.x;
    const int j0  = blockIdx.x * NH;

    // Load the 12 gate rows of w_hh (row = g*512 + j0 + jj, cc = g*4 + jj)
    for (int q = tid; q < 12 * 128; q += SCAN_THREADS) {   // float4 granularity
        int cc = q >> 7;
        int kk = (q & 127) * 4;
        int row = (cc >> 2) * Hd + j0 + (cc & 3);
        float4 v = *(const float4*)&w_hh[(size_t)row * Hd + kk];
        float* w = &ws[cc * WS_STRIDE + kk];
        w[0] = v.x; w[1] = v.y; w[2] = v.z; w[3] = v.w;
    }

    // Per-thread roles
    const int r  = tid % 192;
    const int bb = r & 15;
    const int cc = r >> 4;           // 0..11
    const int s  = tid / 192;        // K split
    const int kbeg = s * 256;
    const float* wrow = &ws[cc * WS_STRIDE + kbeg];

    // Gate-thread constants (tid < 64): (jj, b)
    const int gjj = tid >> 4;        // 0..3 (only valid for tid<64)
    const int gb  = tid & 15;
    const int gj  = j0 + gjj;
    float bhr = 0.f, bhz = 0.f, bhn = 0.f;
    if (tid < 64) {
        bhr = b_hh[gj];
        bhz = b_hh[Hd + gj];
        bhn = b_hh[2 * Hd + gj];
    }
    __syncthreads();

    for (int t = 0; t < Tt; t++) {
        // Prefetch this step's input projections (DRAM latency hidden by compute)
        float xr = 0.f, xz = 0.f, xn = 0.f;
        if (tid < 64) {
            size_t base = ((size_t)gb * Tt + t) * G3 + gj;
            xr = xp[base];
            xz = xp[base + Hd];
            xn = xp[base + 2 * Hd];
        }

        // Load h_{t-1} into smem (t=0: zeros)
        if (t == 0) {
            float4 z4 = make_float4(0.f, 0.f, 0.f, 0.f);
            for (int i = tid; i < (Hd * Bz) / 4; i += SCAN_THREADS)
                ((float4*)hs)[i] = z4;
        } else {
            const float4* src = (const float4*)g_h[(t + 1) & 1];
            for (int i = tid; i < (Hd * Bz) / 4; i += SCAN_THREADS)
                ((float4*)hs)[i] = src[i];
        }
        __syncthreads();

        // gh[bb][cc] partial over k in [kbeg, kbeg+256)
        float a0 = 0.f, a1 = 0.f, a2 = 0.f, a3 = 0.f;
#pragma unroll 8
        for (int k = 0; k < 256; k += 4) {
            float4 w = *(const float4*)(wrow + k);
            int kk = kbeg + k;
            a0 = fmaf(hs[(kk + 0) * Bz + bb], w.x, a0);
            a1 = fmaf(hs[(kk + 1) * Bz + bb], w.y, a1);
            a2 = fmaf(hs[(kk + 2) * Bz + bb], w.z, a2);
            a3 = fmaf(hs[(kk + 3) * Bz + bb], w.w, a3);
        }
        red[s * 192 + cc * 16 + bb] = (a0 + a1) + (a2 + a3);
        __syncthreads();

        // Gate math + state update on 64 threads
        if (tid < 64) {
            float gr = red[gjj * 16 + gb]        + red[192 + gjj * 16 + gb]        + bhr;
            float gz = red[(4 + gjj) * 16 + gb]  + red[192 + (4 + gjj) * 16 + gb]  + bhz;
            float gn = red[(8 + gjj) * 16 + gb]  + red[192 + (8 + gjj) * 16 + gb]  + bhn;
            float rg = sigmoidf_(xr + gr);
            float zg = sigmoidf_(xz + gz);
            float ng = tanhf(xn + rg * gn);
            float hp = hs[gj * Bz + gb];
            float hn = (1.0f - zg) * ng + zg * hp;
            g_h[t & 1][gj * Bz + gb] = hn;
            float ov = do_gelu ? gelu_erf(hn) : hn;
            out[((size_t)gb * Tt + t) * Hd + gj] = ov;
        }
        grid_barrier();
    }
}

// ---------------------------------------------------------------------------
extern "C" void kernel_launch(void* const* d_in, const int* in_sizes, int n_in,
                              void* d_out, int out_size)
{
    const float* x     = (const float*)d_in[0];
    const float* w_ih1 = (const float*)d_in[1];
    const float* w_hh1 = (const float*)d_in[2];
    const float* b_ih1 = (const float*)d_in[3];
    const float* b_hh1 = (const float*)d_in[4];
    const float* w_ih2 = (const float*)d_in[5];
    const float* w_hh2 = (const float*)d_in[6];
    const float* b_ih2 = (const float*)d_in[7];
    const float* b_hh2 = (const float*)d_in[8];
    float* y = (float*)d_out;

    float *xp, *a;
    cudaGetSymbolAddress((void**)&xp, g_xp);
    cudaGetSymbolAddress((void**)&a,  g_a);

    const int scan_smem = (Hd * Bz + 12 * WS_STRIDE + 2 * 12 * 16) * (int)sizeof(float);
    cudaFuncSetAttribute(gru_scan, cudaFuncAttributeMaxDynamicSharedMemorySize, scan_smem);

    dim3 ggrid(G3 / 128, (Bz * Tt) / 128);   // 12 x 512

    // Layer 1
    gemm_nt_bias<<<ggrid, 256>>>(x, w_ih1, b_ih1, xp);
    gru_scan<<<NB, SCAN_THREADS, scan_smem>>>(xp, w_hh1, b_hh1, a, 1);

    // Layer 2 (xp buffer reused; scan1 has fully consumed xp1 by stream order)
    gemm_nt_bias<<<ggrid, 256>>>(a, w_ih2, b_ih2, xp);
    gru_scan<<<NB, SCAN_THREADS, scan_smem>>>(xp, w_hh2, b_hh2, y, 0);
}

// round 4
// speedup vs baseline: 1.2028x; 1.2028x over previous
#include <cuda_runtime.h>
#include <math.h>
#include <stdint.h>

// Problem dims (fixed)
#define Bz 16
#define Tt 4096
#define Hd 512
#define G3 1536            // 3*Hd

// Cluster scan config
#define CL 16              // CTAs per cluster (non-portable size)
#define NCL 8              // clusters (each owns 2 batch elements)
#define NBLK (CL*NCL)      // 128 CTAs
#define SCAN_THREADS 384   // 12 warps
#define JPC 32             // hidden units per CTA
#define ROWS_PER_CTA 96    // 3 gates * JPC
#define WS_STRIDE 516      // 512 + 4 pad (conflict-free lane-strided LDS.128)

// smem layout (floats)
#define WS_FLOATS (ROWS_PER_CTA * WS_STRIDE)   // 49536
#define HS_OFF    WS_FLOATS
#define HS_BUF    (2 * Hd)                     // [b][k] per buffer = 1024 floats
#define RED_OFF   (HS_OFF + 2 * HS_BUF)
#define RED_FLOATS (ROWS_PER_CTA * 4 * 2)      // [cc][ks][b] = 768
#define SMEM_FLOATS (RED_OFF + RED_FLOATS)     // 52352 floats = 209408 B

// ---------------------------------------------------------------------------
// Scratch (device globals; no allocation allowed)
// ---------------------------------------------------------------------------
__device__ float g_xp[(size_t)Bz * Tt * G3];    // xp1, then reused for xp2
__device__ float g_a [(size_t)Bz * Tt * Hd];    // gelu(h1)

// ---------------------------------------------------------------------------
// Packed fp32x2 helpers (Blackwell FFMA2 via PTX)
// ---------------------------------------------------------------------------
__device__ __forceinline__ unsigned long long ffma2(unsigned long long a,
                                                    unsigned long long b,
                                                    unsigned long long c)
{
    unsigned long long d;
    asm("fma.rn.f32x2 %0, %1, %2, %3;" : "=l"(d) : "l"(a), "l"(b), "l"(c));
    return d;
}
__device__ __forceinline__ float f2lo(unsigned long long v) { return __uint_as_float((unsigned)v); }
__device__ __forceinline__ float f2hi(unsigned long long v) { return __uint_as_float((unsigned)(v >> 32)); }

__device__ __forceinline__ uint32_t smem_u32(const void* p)
{
    uint32_t a;
    asm("{ .reg .u64 t; cvta.to.shared.u64 t, %1; cvt.u32.u64 %0, t; }" : "=r"(a) : "l"(p));
    return a;
}
__device__ __forceinline__ void sts_cluster_f32(uint32_t laddr, int rank, float v)
{
    uint32_t r;
    asm volatile("mapa.shared::cluster.u32 %0, %1, %2;" : "=r"(r) : "r"(laddr), "r"(rank));
    asm volatile("st.shared::cluster.f32 [%0], %1;" :: "r"(r), "f"(v) : "memory");
}
__device__ __forceinline__ void cluster_arrive() {
    asm volatile("barrier.cluster.arrive.aligned;" ::: "memory");
}
__device__ __forceinline__ void cluster_wait() {
    asm volatile("barrier.cluster.wait.aligned;" ::: "memory");
}

__device__ __forceinline__ float sigmoidf_(float x) { return 1.0f / (1.0f + expf(-x)); }
__device__ __forceinline__ float gelu_erf(float x) {
    return 0.5f * x * (1.0f + erff(x * 0.70710678118654752f));
}

// ---------------------------------------------------------------------------
// GEMM: C[M][1536] = A[M][512] * W[1536][512]^T + bias[1536]
// 128x128 tile, 256 threads, 8x8 per thread via FFMA2 (4 row-pairs x 8 dup-cols).
// B operands stored pre-duplicated in smem ({v,v}) so no per-k packing ALU.
// ---------------------------------------------------------------------------
__global__ __launch_bounds__(256, 2) void gemm_nt_bias(
    const float* __restrict__ A, const float* __restrict__ W,
    const float* __restrict__ bias, float* __restrict__ C)
{
    __shared__ float as[16][132];
    __shared__ float bs2[16][268];     // duplicated: bs2[k][2j] = bs2[k][2j+1] = b[j]

    const int m0 = blockIdx.y * 128;
    const int n0 = blockIdx.x * 128;
    const int tid = threadIdx.x;
    const int tx = tid & 15;        // n direction
    const int ty = tid >> 4;        // m direction

    unsigned long long acc[4][8];
#pragma unroll
    for (int i = 0; i < 4; i++)
#pragma unroll
        for (int j = 0; j < 8; j++) acc[i][j] = 0ull;

    for (int kc = 0; kc < 512; kc += 16) {
#pragma unroll
        for (int it = 0; it < 2; it++) {
            int f = tid + it * 256;          // 0..511
            int row = f >> 2;
            int kq = (f & 3) * 4;
            float4 va = *(const float4*)&A[(size_t)(m0 + row) * 512 + kc + kq];
            as[kq + 0][row] = va.x; as[kq + 1][row] = va.y;
            as[kq + 2][row] = va.z; as[kq + 3][row] = va.w;
            float4 vb = *(const float4*)&W[(size_t)(n0 + row) * 512 + kc + kq];
            *(float2*)&bs2[kq + 0][2 * row] = make_float2(vb.x, vb.x);
            *(float2*)&bs2[kq + 1][2 * row] = make_float2(vb.y, vb.y);
            *(float2*)&bs2[kq + 2][2 * row] = make_float2(vb.z, vb.z);
            *(float2*)&bs2[kq + 3][2 * row] = make_float2(vb.w, vb.w);
        }
        __syncthreads();

#pragma unroll
        for (int k = 0; k < 16; k++) {
            ulonglong2 aA = *(const ulonglong2*)&as[k][ty * 4];       // rows r0r1, r2r3
            ulonglong2 aB = *(const ulonglong2*)&as[k][64 + ty * 4];
            ulonglong2 b0 = *(const ulonglong2*)&bs2[k][8 * tx];
            ulonglong2 b1 = *(const ulonglong2*)&bs2[k][8 * tx + 4];
            ulonglong2 b2 = *(const ulonglong2*)&bs2[k][128 + 8 * tx];
            ulonglong2 b3 = *(const ulonglong2*)&bs2[k][128 + 8 * tx + 4];
            unsigned long long ap[4] = { aA.x, aA.y, aB.x, aB.y };
            unsigned long long bd[8] = { b0.x, b0.y, b1.x, b1.y, b2.x, b2.y, b3.x, b3.y };
#pragma unroll
            for (int ip = 0; ip < 4; ip++)
#pragma unroll
                for (int j = 0; j < 8; j++)
                    acc[ip][j] = ffma2(ap[ip], bd[j], acc[ip][j]);
        }
        __syncthreads();
    }

    // Epilogue. acc[ip][j]: lo = row pair even, hi = row pair odd.
    float4 bv0 = *(const float4*)&bias[n0 + tx * 4];
    float4 bv1 = *(const float4*)&bias[n0 + 64 + tx * 4];
    const float bj[8] = { bv0.x, bv0.y, bv0.z, bv0.w, bv1.x, bv1.y, bv1.z, bv1.w };
#pragma unroll
    for (int ip = 0; ip < 4; ip++) {
#pragma unroll
        for (int half = 0; half < 2; half++) {
            int m = m0 + ((ip >> 1) ? 64 : 0) + ty * 4 + (ip & 1) * 2 + half;
            float o[8];
#pragma unroll
            for (int j = 0; j < 8; j++)
                o[j] = (half ? f2hi(acc[ip][j]) : f2lo(acc[ip][j])) + bj[j];
            *(float4*)&C[(size_t)m * G3 + n0 + tx * 4]      = make_float4(o[0], o[1], o[2], o[3]);
            *(float4*)&C[(size_t)m * G3 + n0 + 64 + tx * 4] = make_float4(o[4], o[5], o[6], o[7]);
        }
    }
}

// ---------------------------------------------------------------------------
// Cluster-based GRU scan.
// 8 clusters x 16 CTAs. Cluster c owns batch {2c, 2c+1}. CTA rank r owns hidden
// units j in [32r, 32r+32) (96 gate-rows of w_hh resident in smem, 192KB).
// h state replicated per-CTA in smem [buf][b][k]; gate threads broadcast h_new
// to all 16 ranks via DSMEM stores; one barrier.cluster per timestep.
// Warp layout: warp = (ccg 0..2, ks 0..3); lane = cc within group; each lane
// computes both batch elements with FFMA2 over k-pairs.
// ---------------------------------------------------------------------------
__global__ __launch_bounds__(SCAN_THREADS, 1) void gru_scan_cl(
    const float* __restrict__ xp, const float* __restrict__ w_hh,
    const float* __restrict__ b_hh, float* __restrict__ out, int do_gelu)
{
    extern __shared__ float sm[];
    float* ws  = sm;                  // [96][516]
    float* hs  = sm + HS_OFF;         // [2][2][512]
    float* red = sm + RED_OFF;        // [96][4][2]

    const int tid = threadIdx.x;
    uint32_t rank;
    asm("mov.u32 %0, %%cluster_ctarank;" : "=r"(rank));
    const int cid = blockIdx.x >> 4;       // cluster id 0..7
    const int j0 = rank * JPC;

    // Load 96 gate rows of w_hh: cc = g*32 + jj -> row g*512 + j0 + jj
    for (int idx = tid; idx < ROWS_PER_CTA * 128; idx += SCAN_THREADS) {
        int cc = idx >> 7;
        int kq = (idx & 127) * 4;
        int g = cc >> 5, jj = cc & 31;
        float4 v = *(const float4*)&w_hh[(size_t)(g * Hd + j0 + jj) * Hd + kq];
        float* w = &ws[cc * WS_STRIDE + kq];
        w[0] = v.x; w[1] = v.y; w[2] = v.z; w[3] = v.w;
    }
    // Zero h buffer 0
    for (int i = tid; i < HS_BUF; i += SCAN_THREADS) hs[i] = 0.f;
    __syncthreads();

    // FMA roles
    const int warp = tid >> 5, lane = tid & 31;
    const int ks = warp & 3;
    const int cc = (warp >> 2) * 32 + lane;      // 0..95
    const int k0 = ks * 128;
    const float* wrow = &ws[cc * WS_STRIDE + k0];

    // Gate roles (tid < 64): (jj = tid>>1, b = tid&1)
    const int gjj = tid >> 1;
    const int gb  = tid & 1;
    const int gjl = j0 + gjj;
    float bhr = 0.f, bhz = 0.f, bhn = 0.f;
    const float* xpp = xp;
    float* outp = out;
    if (tid < 64) {
        bhr = b_hh[gjl];
        bhz = b_hh[Hd + gjl];
        bhn = b_hh[2 * Hd + gjl];
        int bg = cid * 2 + gb;
        xpp  = xp  + (size_t)bg * Tt * G3 + gjl;
        outp = out + (size_t)bg * Tt * Hd + gjl;
    }
    const uint32_t smb = smem_u32(sm);

    for (int t = 0; t < Tt; t++) {
        const int cur = t & 1, nxt = cur ^ 1;

        // Prefetch xp for this step (latency hidden under FMA loop)
        float xr = 0.f, xz = 0.f, xn = 0.f;
        if (tid < 64) {
            xr = __ldg(xpp);
            xz = __ldg(xpp + Hd);
            xn = __ldg(xpp + 2 * Hd);
        }

        const float* h0 = &hs[cur * HS_BUF + k0];        // batch 0 row
        const float* h1 = &hs[cur * HS_BUF + Hd + k0];   // batch 1 row
        unsigned long long a0a = 0ull, a0b = 0ull, a1a = 0ull, a1b = 0ull;
#pragma unroll 8
        for (int kq = 0; kq < 128; kq += 4) {
            ulonglong2 wv  = *(const ulonglong2*)(wrow + kq);  // {w[k],w[k+1]},{w[k+2],w[k+3]}
            ulonglong2 h0v = *(const ulonglong2*)(h0 + kq);    // broadcast (same addr all lanes)
            ulonglong2 h1v = *(const ulonglong2*)(h1 + kq);
            a0a = ffma2(wv.x, h0v.x, a0a);
            a0b = ffma2(wv.y, h0v.y, a0b);
            a1a = ffma2(wv.x, h1v.x, a1a);
            a1b = ffma2(wv.y, h1v.y, a1b);
        }
        float2 p;
        p.x = (f2lo(a0a) + f2hi(a0a)) + (f2lo(a0b) + f2hi(a0b));
        p.y = (f2lo(a1a) + f2hi(a1a)) + (f2lo(a1b) + f2hi(a1b));
        *(float2*)&red[(cc * 4 + ks) * 2] = p;
        __syncthreads();

        if (tid < 64) {
            const float* rr = &red[gb];
            int base = gjj * 8;
            float gr = (rr[base]       + rr[base + 2])       + (rr[base + 4]       + rr[base + 6]);
            float gz = (rr[256 + base] + rr[256 + base + 2]) + (rr[256 + base + 4] + rr[256 + base + 6]);
            float gn = (rr[512 + base] + rr[512 + base + 2]) + (rr[512 + base + 4] + rr[512 + base + 6]);
            float rg = sigmoidf_(xr + gr + bhr);
            float zg = sigmoidf_(xz + gz + bhz);
            float ng = tanhf(xn + rg * (gn + bhn));
            float hp = hs[cur * HS_BUF + gb * Hd + gjl];
            float hnew = (1.0f - zg) * ng + zg * hp;

            // Broadcast h_new to all 16 CTAs of the cluster (incl. self)
            uint32_t laddr = smb + (uint32_t)((HS_OFF + nxt * HS_BUF + gb * Hd + gjl) * 4);
#pragma unroll
            for (int rd = 0; rd < CL; rd++) sts_cluster_f32(laddr, rd, hnew);

            *outp = do_gelu ? gelu_erf(hnew) : hnew;
            xpp += G3;
            outp += Hd;
        }
        cluster_arrive();   // release: orders DSMEM stores
        cluster_wait();     // acquire: h_new visible in local hs[nxt]
    }
}

// ---------------------------------------------------------------------------
extern "C" void kernel_launch(void* const* d_in, const int* in_sizes, int n_in,
                              void* d_out, int out_size)
{
    const float* x     = (const float*)d_in[0];
    const float* w_ih1 = (const float*)d_in[1];
    const float* w_hh1 = (const float*)d_in[2];
    const float* b_ih1 = (const float*)d_in[3];
    const float* b_hh1 = (const float*)d_in[4];
    const float* w_ih2 = (const float*)d_in[5];
    const float* w_hh2 = (const float*)d_in[6];
    const float* b_ih2 = (const float*)d_in[7];
    const float* b_hh2 = (const float*)d_in[8];
    float* y = (float*)d_out;

    float *xp, *a;
    cudaGetSymbolAddress((void**)&xp, g_xp);
    cudaGetSymbolAddress((void**)&a,  g_a);

    const int scan_smem = SMEM_FLOATS * (int)sizeof(float);   // 209408 B
    cudaFuncSetAttribute(gru_scan_cl, cudaFuncAttributeMaxDynamicSharedMemorySize, scan_smem);
    cudaFuncSetAttribute(gru_scan_cl, cudaFuncAttributeNonPortableClusterSizeAllowed, 1);

    cudaLaunchConfig_t cfg = {};
    cfg.gridDim = dim3(NBLK, 1, 1);
    cfg.blockDim = dim3(SCAN_THREADS, 1, 1);
    cfg.dynamicSmemBytes = scan_smem;
    cfg.stream = 0;
    cudaLaunchAttribute attrs[1];
    attrs[0].id = cudaLaunchAttributeClusterDimension;
    attrs[0].val.clusterDim.x = CL;
    attrs[0].val.clusterDim.y = 1;
    attrs[0].val.clusterDim.z = 1;
    cfg.attrs = attrs;
    cfg.numAttrs = 1;

    dim3 ggrid(G3 / 128, (Bz * Tt) / 128);   // 12 x 512

    // Layer 1
    gemm_nt_bias<<<ggrid, 256>>>(x, w_ih1, b_ih1, xp);
    cudaLaunchKernelEx(&cfg, gru_scan_cl, xp, w_hh1, b_hh1, a, 1);

    // Layer 2 (xp reused; scan1 fully consumed xp1 by stream order)
    gemm_nt_bias<<<ggrid, 256>>>(a, w_ih2, b_ih2, xp);
    cudaLaunchKernelEx(&cfg, gru_scan_cl, xp, w_hh2, b_hh2, y, 0);
}